// round 11
// baseline (speedup 1.0000x reference)
#include <cuda_runtime.h>
#include <cuda_fp16.h>
#include <cstdint>
#include <math.h>

#define Bb 4
#define Mm 2048
#define Cc 512
#define Hh 8
#define BHt 32
#define VTR 72                         // VT rows per bh: 64 V + 1 mask + 7 zero pad

#define QSCALE 0.36067376022224085f    // 0.25 * log2(e)

// fp16 staging
__device__ __half g_WT[768 * Cc];          // (j, k): Wq^T*QSCALE | Wk^T | Wv^T
__device__ __half g_Qh[BHt * Mm * 16];     // (bh, m, 16)  pre-scaled by QSCALE
__device__ __half g_Kh[BHt * Mm * 16];     // (bh, m, 16)
__device__ __half g_VTh[BHt * VTR * Mm];   // (bh, d, m); d=64 mask row; 65-71 zero

__device__ __forceinline__ uint32_t smem_u32(const void* p) {
    uint32_t a;
    asm("{ .reg .u64 t; cvta.to.shared.u64 t, %1; cvt.u32.u64 %0, t; }"
        : "=r"(a) : "l"(p));
    return a;
}
__device__ __forceinline__ void ldm4(uint32_t r[4], uint32_t addr) {
    asm volatile("ldmatrix.sync.aligned.m8n8.x4.shared.b16 {%0,%1,%2,%3}, [%4];"
                 : "=r"(r[0]), "=r"(r[1]), "=r"(r[2]), "=r"(r[3]) : "r"(addr));
}
__device__ __forceinline__ void ldm2(uint32_t r[2], uint32_t addr) {
    asm volatile("ldmatrix.sync.aligned.m8n8.x2.shared.b16 {%0,%1}, [%2];"
                 : "=r"(r[0]), "=r"(r[1]) : "r"(addr));
}
__device__ __forceinline__ void mma16816(float c[4], const uint32_t a[4],
                                         uint32_t b0, uint32_t b1) {
    asm volatile("mma.sync.aligned.m16n8k16.row.col.f32.f16.f16.f32 "
                 "{%0,%1,%2,%3}, {%4,%5,%6,%7}, {%8,%9}, {%0,%1,%2,%3};"
                 : "+f"(c[0]), "+f"(c[1]), "+f"(c[2]), "+f"(c[3])
                 : "r"(a[0]), "r"(a[1]), "r"(a[2]), "r"(a[3]), "r"(b0), "r"(b1));
}
// P = ex2(relu(.)) on a packed pair; returns half2 as uint32
__device__ __forceinline__ uint32_t exp_relu_pack(float lo, float hi) {
    uint32_t h, r;
    asm("cvt.rn.f16x2.f32 %0, %1, %2;" : "=r"(h) : "f"(hi), "f"(lo));
    asm("max.f16x2 %0, %0, %1;" : "+r"(h) : "r"(0u));
    asm("ex2.approx.f16x2 %0, %1;" : "=r"(r) : "r"(h));
    return r;
}
#define CP16(dst, src) \
    asm volatile("cp.async.ca.shared.global [%0], [%1], 16;" :: "r"(dst), "l"(src))
#define CP_COMMIT() asm volatile("cp.async.commit_group;")
#define CP_WAIT1()  asm volatile("cp.async.wait_group 1;")
#define CP_WAIT0()  asm volatile("cp.async.wait_group 0;")

__device__ __forceinline__ uint4 f8_to_h8(float4 a, float4 b) {
    __half2 h0 = __floats2half2_rn(a.x, a.y), h1 = __floats2half2_rn(a.z, a.w);
    __half2 h2 = __floats2half2_rn(b.x, b.y), h3 = __floats2half2_rn(b.z, b.w);
    uint4 u;
    u.x = *(uint32_t*)&h0; u.y = *(uint32_t*)&h1;
    u.z = *(uint32_t*)&h2; u.w = *(uint32_t*)&h3;
    return u;
}

// ---------------------------------------------------------------------------
// Weight conversion + VT mask row fill. 8 elements/thread (MLP 8).
// ---------------------------------------------------------------------------
__global__ void conv_w_kernel(const float* __restrict__ Wq,
                              const float* __restrict__ Wk,
                              const float* __restrict__ Wv,
                              const int* __restrict__ mask)
{
    const int t = blockIdx.x * 256 + threadIdx.x;
    if (t < 49152) {                       // 768*512/8 weight chunks
        const int j  = t >> 6;
        const int k0 = (t & 63) * 8;
        const float* src; int lds; int jj; float sc = 1.0f;
        if (j < 128)      { src = Wq; lds = 128; jj = j;       sc = QSCALE; }
        else if (j < 256) { src = Wk; lds = 128; jj = j - 128; }
        else              { src = Wv; lds = 512; jj = j - 256; }
        __align__(16) __half tmp[8];
#pragma unroll
        for (int i = 0; i < 8; i++)
            tmp[i] = __float2half_rn(src[(size_t)(k0 + i) * lds + jj] * sc);
        *(uint4*)&g_WT[j * Cc + k0] = *(uint4*)tmp;
    } else {                               // mask rows: 65536/8 chunks
        const int i2 = (t - 49152) * 8;
        const int bh = i2 >> 11;
        const int m  = i2 & 2047;
        __align__(16) __half tmp[8];
#pragma unroll
        for (int i = 0; i < 8; i++)
            tmp[i] = __float2half_rn((float)mask[(bh >> 3) * Mm + m + i]);
        *(uint4*)&g_VTh[((size_t)bh * VTR + 64) * Mm + m] = *(uint4*)tmp;
    }
}

// ---------------------------------------------------------------------------
// Kernel 1: HMMA QKV projection; coalesced epilogue via smem transpose.
// ---------------------------------------------------------------------------
__global__ __launch_bounds__(256) void proj_kernel(
    const float* __restrict__ x, const int* __restrict__ mask,
    const float* __restrict__ bq, const float* __restrict__ bk,
    const float* __restrict__ bv)
{
    __shared__ __align__(16) char SM[40960];   // mainloop: A(2x10240)+B(2x10240); epilogue: 128x272 stage
    char* Ah0 = SM;
    char* Bh0 = SM + 20480;

    const int row0 = blockIdx.x * 128;
    const int col0 = blockIdx.y * 128;
    const int tid  = threadIdx.x;
    const int lane = tid & 31;
    const int wid  = tid >> 5;
    const int wm   = wid & 3;
    const int wn   = wid >> 2;

    const int rowi = lane & 7;
    const int rsel = (lane >> 4) & 1;
    const int csel = (lane >> 3) & 1;
    const int g    = lane >> 2;
    const int tig  = lane & 3;

    const uint32_t AhA = smem_u32(Ah0);
    const uint32_t BhA = smem_u32(Bh0);

    const int r0 = (tid * 2) >> 2, s0 = (tid * 2) & 3;
    const int r1 = (tid * 2 + 1) >> 2, s1 = (tid * 2 + 1) & 3;

    const float* xa0 = x + (size_t)(row0 + r0) * Cc + s0 * 8;
    const float* xa1 = x + (size_t)(row0 + r1) * Cc + s1 * 8;
    const __half* wb0 = g_WT + (size_t)(col0 + r0) * Cc + s0 * 8;
    const __half* wb1 = g_WT + (size_t)(col0 + r1) * Cc + s1 * 8;

    {
        float4 a00 = *(const float4*)xa0, a01 = *(const float4*)(xa0 + 4);
        float4 a10 = *(const float4*)xa1, a11 = *(const float4*)(xa1 + 4);
        *(uint4*)(Ah0 + r0 * 80 + s0 * 16) = f8_to_h8(a00, a01);
        *(uint4*)(Ah0 + r1 * 80 + s1 * 16) = f8_to_h8(a10, a11);
        *(uint4*)(Bh0 + r0 * 80 + s0 * 16) = *(const uint4*)wb0;
        *(uint4*)(Bh0 + r1 * 80 + s1 * 16) = *(const uint4*)wb1;
    }
    __syncthreads();

    float acc[2][8][4] = {};

    for (int it = 0; it < 16; it++) {
        float4 a00, a01, a10, a11;
        uint4 pb0, pb1;
        if (it < 15) {
            const int kn = (it + 1) * 32;
            a00 = *(const float4*)(xa0 + kn);
            a01 = *(const float4*)(xa0 + kn + 4);
            a10 = *(const float4*)(xa1 + kn);
            a11 = *(const float4*)(xa1 + kn + 4);
            pb0 = *(const uint4*)(wb0 + kn);
            pb1 = *(const uint4*)(wb1 + kn);
        }
        const uint32_t Ab = AhA + (uint32_t)(it & 1) * 10240u;
        const uint32_t Bc = BhA + (uint32_t)(it & 1) * 10240u;
#pragma unroll
        for (int ks = 0; ks < 2; ks++) {
            uint32_t qa[2][4];
#pragma unroll
            for (int mt = 0; mt < 2; mt++)
                ldm4(qa[mt], Ab + (wm * 32 + mt * 16 + rowi + csel * 8) * 80
                              + ks * 32 + rsel * 16);
#pragma unroll
            for (int nb = 0; nb < 4; nb++) {
                uint32_t kb[4];
                ldm4(kb, Bc + (wn * 64 + nb * 16 + rowi + rsel * 8) * 80
                           + ks * 32 + csel * 16);
                mma16816(acc[0][nb * 2],     qa[0], kb[0], kb[1]);
                mma16816(acc[0][nb * 2 + 1], qa[0], kb[2], kb[3]);
                mma16816(acc[1][nb * 2],     qa[1], kb[0], kb[1]);
                mma16816(acc[1][nb * 2 + 1], qa[1], kb[2], kb[3]);
            }
        }
        if (it < 15) {
            char* An = Ah0 + ((it + 1) & 1) * 10240;
            char* Bn = Bh0 + ((it + 1) & 1) * 10240;
            *(uint4*)(An + r0 * 80 + s0 * 16) = f8_to_h8(a00, a01);
            *(uint4*)(An + r1 * 80 + s1 * 16) = f8_to_h8(a10, a11);
            *(uint4*)(Bn + r0 * 80 + s0 * 16) = pb0;
            *(uint4*)(Bn + r1 * 80 + s1 * 16) = pb1;
            __syncthreads();
        }
    }

    // ---------------- epilogue: stage [j][m] tile in smem, write coalesced ----
    __syncthreads();                    // mainloop smem reads done; reuse SM
    __half* St = (__half*)SM;           // pitch 136 halves (272 B), 128 rows
    const int b     = row0 >> 11;
    const int row0m = row0 & (Mm - 1);
    const bool isV  = (col0 >= 256);
    const bool isQ  = (col0 == 0);

#pragma unroll
    for (int mt = 0; mt < 2; mt++) {
        const int mA = wm * 32 + mt * 16 + g;
        const int mB = mA + 8;
        float ska = 1.0f, skb = 1.0f;
        if (isV) {
            ska = (float)mask[b * Mm + row0m + mA];
            skb = (float)mask[b * Mm + row0m + mB];
        }
#pragma unroll
        for (int j = 0; j < 8; j++) {
            const int vj = wn * 64 + j * 8 + tig * 2;
            float b0, b1;
            if (isQ)              { b0 = bq[vj] * QSCALE; b1 = bq[vj + 1] * QSCALE; }
            else if (col0 == 128) { b0 = bk[vj];          b1 = bk[vj + 1]; }
            else { b0 = bv[col0 - 256 + vj]; b1 = bv[col0 - 256 + vj + 1]; }
            St[vj * 136 + mA]       = __float2half_rn((acc[mt][j][0] + b0) * ska);
            St[(vj + 1) * 136 + mA] = __float2half_rn((acc[mt][j][1] + b1) * ska);
            St[vj * 136 + mB]       = __float2half_rn((acc[mt][j][2] + b0) * skb);
            St[(vj + 1) * 136 + mB] = __float2half_rn((acc[mt][j][3] + b1) * skb);
        }
    }
    __syncthreads();

    if (!isV) {
        __half* dstbase = isQ ? g_Qh : g_Kh;
#pragma unroll
        for (int r = 0; r < 4; r++) {
            const int idx = r * 256 + tid;        // lanes -> consecutive m
            const int h = idx >> 7, m = idx & 127;
            __align__(16) __half tmp[16];
#pragma unroll
            for (int dq = 0; dq < 16; dq++)
                tmp[dq] = St[(h * 16 + dq) * 136 + m];
            uint4* dst = (uint4*)&dstbase[(((size_t)(b * Hh + h)) * Mm + row0m + m) * 16];
            dst[0] = ((uint4*)tmp)[0];
            dst[1] = ((uint4*)tmp)[1];
        }
    } else {
        const int vj = tid >> 1, seg = tid & 1;
        const int jj = (col0 - 256) + vj;
        const int h = jj >> 6, d = jj & 63;
        const uint4* src = (const uint4*)&St[vj * 136 + seg * 64];
        uint4* dst = (uint4*)&g_VTh[(((size_t)(b * Hh + h)) * VTR + d) * Mm + row0m + seg * 64];
#pragma unroll
        for (int i = 0; i < 8; i++) dst[i] = src[i];
    }
}

// ---------------------------------------------------------------------------
// Kernel 2: HMMA fp16 flash attention (unchanged from R10).
// ---------------------------------------------------------------------------
#define KB 3072
#define VB 10368    // 72 rows * 144B

__global__ __launch_bounds__(128, 4) void attn_kernel(
    const float* __restrict__ gamma, float* __restrict__ out)
{
    __shared__ __align__(16) char Qs[128 * 48];
    __shared__ __align__(16) char Ks[2][64 * 48];
    __shared__ __align__(16) char Vs[2][VTR * 144];

    const int tid  = threadIdx.x;
    const int w    = tid >> 5;
    const int lane = tid & 31;
    const int g    = lane >> 2;
    const int tig  = lane & 3;

    const int bh = blockIdx.x >> 4;
    const int mt = blockIdx.x & 15;
    const int b  = bh >> 3;
    const int h  = bh & 7;
    const int m0 = mt * 128;

    const uint32_t QsA = smem_u32(Qs);
    const uint32_t KsA = smem_u32(Ks);
    const uint32_t VsA = smem_u32(Vs);

    {
        const uint4* q4 = (const uint4*)(g_Qh + ((size_t)bh * Mm + m0 + tid) * 16);
        *(uint4*)(Qs + tid * 48)      = q4[0];
        *(uint4*)(Qs + tid * 48 + 16) = q4[1];
    }

    const __half* vsrc0 = g_VTh + ((size_t)bh * VTR + (tid >> 1)) * Mm + (tid & 1) * 32;
    const uint32_t vdst0 = VsA + (uint32_t)((tid >> 1) * 144 + (tid & 1) * 64);
    const __half* esrc0 = g_VTh + ((size_t)bh * VTR + 64 + (tid >> 3)) * Mm + (tid & 7) * 8;
    const uint32_t edst0 = VsA + (uint32_t)((64 + (tid >> 3)) * 144 + (tid & 7) * 16);
    const __half* ksrc0 = g_Kh + ((size_t)bh * Mm + tid) * 16;
    const uint32_t kdst0 = KsA + (uint32_t)(tid * 48);

    auto issue_tile = [&](int nt, int buf) {
        const int n0 = nt * 64;
        const __half* vs = vsrc0 + n0;
        const uint32_t vd = vdst0 + (uint32_t)buf * VB;
        CP16(vd,      vs);
        CP16(vd + 16, vs + 8);
        CP16(vd + 32, vs + 16);
        CP16(vd + 48, vs + 24);
        if (tid < 64) {
            const __half* ks = ksrc0 + (size_t)n0 * 16;
            const uint32_t kd = kdst0 + (uint32_t)buf * KB;
            CP16(kd,      ks);
            CP16(kd + 16, ks + 8);
            CP16(edst0 + (uint32_t)buf * VB, esrc0 + n0);
        }
    };

    issue_tile(0, 0);
    CP_COMMIT();
    __syncthreads();

    const int rsel = (lane >> 4) & 1;
    const int csel = (lane >> 3) & 1;
    const int rowi = (lane & 7);

    uint32_t qa[2][4];
#pragma unroll
    for (int mt2 = 0; mt2 < 2; mt2++)
        ldm4(qa[mt2], QsA + (w * 32 + mt2 * 16 + rowi + csel * 8) * 48 + rsel * 16);

    float o[2][8][4] = {};
    float oex[2][4] = {};

    const int knrow = rowi + rsel * 8;
    const int kcol  = csel * 16;
    const int ecol  = csel * 16;

    for (int nt = 0; nt < 32; nt++) {
        const int buf = nt & 1;
        if (nt + 1 < 32) {
            issue_tile(nt + 1, buf ^ 1);
            CP_COMMIT();
            CP_WAIT1();
        } else {
            CP_WAIT0();
        }
        __syncthreads();

        const uint32_t Kb = KsA + (uint32_t)buf * KB;
        const uint32_t Vb = VsA + (uint32_t)buf * VB;

#pragma unroll
        for (int kn = 0; kn < 4; kn++) {
            uint32_t kb[4];
            ldm4(kb, Kb + (kn * 16 + knrow) * 48 + kcol);

            uint32_t pa[2][4];
#pragma unroll
            for (int mt2 = 0; mt2 < 2; mt2++) {
                float c0[4] = {}, c1[4] = {};
                mma16816(c0, qa[mt2], kb[0], kb[1]);
                mma16816(c1, qa[mt2], kb[2], kb[3]);
                pa[mt2][0] = exp_relu_pack(c0[0], c0[1]);
                pa[mt2][1] = exp_relu_pack(c0[2], c0[3]);
                pa[mt2][2] = exp_relu_pack(c1[0], c1[1]);
                pa[mt2][3] = exp_relu_pack(c1[2], c1[3]);
            }

#pragma unroll
            for (int p = 0; p < 4; p++) {
                uint32_t vb[4];
                ldm4(vb, Vb + (p * 16 + knrow) * 144 + kn * 32 + kcol);
                mma16816(o[0][2 * p],     pa[0], vb[0], vb[1]);
                mma16816(o[0][2 * p + 1], pa[0], vb[2], vb[3]);
                mma16816(o[1][2 * p],     pa[1], vb[0], vb[1]);
                mma16816(o[1][2 * p + 1], pa[1], vb[2], vb[3]);
            }
            {
                uint32_t eb[2];
                ldm2(eb, Vb + (64 + rowi) * 144 + kn * 32 + ecol);
                mma16816(oex[0], pa[0], eb[0], eb[1]);
                mma16816(oex[1], pa[1], eb[0], eb[1]);
            }
        }
        __syncthreads();
    }

    const float gm = gamma[0];
    float inv[2][2];
#pragma unroll
    for (int mt2 = 0; mt2 < 2; mt2++) {
        const float d0 = __shfl_sync(0xFFFFFFFFu, oex[mt2][0], g << 2);
        const float d1 = __shfl_sync(0xFFFFFFFFu, oex[mt2][2], g << 2);
        inv[mt2][0] = gm / (d0 + 1e-12f);
        inv[mt2][1] = gm / (d1 + 1e-12f);
    }

#pragma unroll
    for (int mt2 = 0; mt2 < 2; mt2++) {
#pragma unroll
        for (int rh = 0; rh < 2; rh++) {
            const int m = m0 + w * 32 + mt2 * 16 + rh * 8 + g;
            float* op = out + ((size_t)b * Mm + m) * Cc + h * 64 + tig * 2;
            const float iv = inv[mt2][rh];
#pragma unroll
            for (int ntile = 0; ntile < 8; ntile++) {
                float2 v;
                v.x = o[mt2][ntile][rh * 2 + 0] * iv;
                v.y = o[mt2][ntile][rh * 2 + 1] * iv;
                *(float2*)(op + ntile * 8) = v;
            }
        }
    }
}

// ---------------------------------------------------------------------------
extern "C" void kernel_launch(void* const* d_in, const int* in_sizes, int n_in,
                              void* d_out, int out_size)
{
    const float* x     = (const float*)d_in[0];
    const int*   mask  = (const int*)  d_in[1];
    const float* Wq    = (const float*)d_in[2];
    const float* bq    = (const float*)d_in[3];
    const float* Wk    = (const float*)d_in[4];
    const float* bk    = (const float*)d_in[5];
    const float* Wv    = (const float*)d_in[6];
    const float* bv    = (const float*)d_in[7];
    const float* gamma = (const float*)d_in[8];
    float* out = (float*)d_out;

    conv_w_kernel<<<224, 256>>>(Wq, Wk, Wv, mask);

    dim3 pg((Bb * Mm) / 128, 6);
    proj_kernel<<<pg, 256>>>(x, mask, bq, bk, bv);

    attn_kernel<<<BHt * (Mm / 128), 128>>>(gamma, out);
}

// round 12
// speedup vs baseline: 1.2493x; 1.2493x over previous
#include <cuda_runtime.h>
#include <cuda_fp16.h>
#include <cstdint>
#include <math.h>

#define Bb 4
#define Mm 2048
#define Cc 512
#define Hh 8
#define BHt 32
#define VTR 72                         // VT rows per bh: 64 V + 1 indicator + 7 zero pad

#define QSCALE 0.36067376022224085f    // 0.25 * log2(e)

// fp16 staging (compacted along keys)
__device__ __half g_WT[768 * Cc];          // (j, k): Wq^T*QSCALE | Wk^T | Wv^T
__device__ __half g_Qh[BHt * Mm * 16];     // (bh, m, 16)  pre-scaled by QSCALE
__device__ __half g_Kh[BHt * Mm * 16];     // (bh, j, 16)  compacted keys
__device__ __half g_VTh[BHt * VTR * Mm];   // (bh, d, j)   compacted; d=64 indicator
__device__ int    g_cidx[Bb * Mm];         // compact position of key m (valid if mask=1)
__device__ int    g_nvalid[Bb];

__device__ __forceinline__ uint32_t smem_u32(const void* p) {
    uint32_t a;
    asm("{ .reg .u64 t; cvta.to.shared.u64 t, %1; cvt.u32.u64 %0, t; }"
        : "=r"(a) : "l"(p));
    return a;
}
__device__ __forceinline__ void ldm4(uint32_t r[4], uint32_t addr) {
    asm volatile("ldmatrix.sync.aligned.m8n8.x4.shared.b16 {%0,%1,%2,%3}, [%4];"
                 : "=r"(r[0]), "=r"(r[1]), "=r"(r[2]), "=r"(r[3]) : "r"(addr));
}
__device__ __forceinline__ void ldm2(uint32_t r[2], uint32_t addr) {
    asm volatile("ldmatrix.sync.aligned.m8n8.x2.shared.b16 {%0,%1}, [%2];"
                 : "=r"(r[0]), "=r"(r[1]) : "r"(addr));
}
__device__ __forceinline__ void mma16816(float c[4], const uint32_t a[4],
                                         uint32_t b0, uint32_t b1) {
    asm volatile("mma.sync.aligned.m16n8k16.row.col.f32.f16.f16.f32 "
                 "{%0,%1,%2,%3}, {%4,%5,%6,%7}, {%8,%9}, {%0,%1,%2,%3};"
                 : "+f"(c[0]), "+f"(c[1]), "+f"(c[2]), "+f"(c[3])
                 : "r"(a[0]), "r"(a[1]), "r"(a[2]), "r"(a[3]), "r"(b0), "r"(b1));
}
__device__ __forceinline__ uint32_t exp_relu_pack(float lo, float hi) {
    uint32_t h, r;
    asm("cvt.rn.f16x2.f32 %0, %1, %2;" : "=r"(h) : "f"(hi), "f"(lo));
    asm("max.f16x2 %0, %0, %1;" : "+r"(h) : "r"(0u));
    asm("ex2.approx.f16x2 %0, %1;" : "=r"(r) : "r"(h));
    return r;
}
#define CP16(dst, src) \
    asm volatile("cp.async.ca.shared.global [%0], [%1], 16;" :: "r"(dst), "l"(src))
#define CP_COMMIT() asm volatile("cp.async.commit_group;")
#define CP_WAIT1()  asm volatile("cp.async.wait_group 1;")
#define CP_WAIT0()  asm volatile("cp.async.wait_group 0;")

__device__ __forceinline__ uint4 f8_to_h8(float4 a, float4 b) {
    __half2 h0 = __floats2half2_rn(a.x, a.y), h1 = __floats2half2_rn(a.z, a.w);
    __half2 h2 = __floats2half2_rn(b.x, b.y), h3 = __floats2half2_rn(b.z, b.w);
    uint4 u;
    u.x = *(uint32_t*)&h0; u.y = *(uint32_t*)&h1;
    u.z = *(uint32_t*)&h2; u.w = *(uint32_t*)&h3;
    return u;
}

// ---------------------------------------------------------------------------
// Order-preserving prefix scan of mask per batch (deterministic compaction).
// ---------------------------------------------------------------------------
__global__ __launch_bounds__(1024) void scan_kernel(const int* __restrict__ mask)
{
    const int b = blockIdx.x;
    const int t = threadIdx.x;          // 0..1023, 2 elements each
    const int m0v = mask[b * Mm + 2 * t];
    const int m1v = mask[b * Mm + 2 * t + 1];
    const int s = m0v + m1v;
    const int lane = t & 31, w = t >> 5;

    int v = s;
#pragma unroll
    for (int off = 1; off < 32; off <<= 1) {
        int u = __shfl_up_sync(0xFFFFFFFFu, v, off);
        if (lane >= off) v += u;
    }
    __shared__ int wsum[32];
    if (lane == 31) wsum[w] = v;
    __syncthreads();
    if (w == 0) {
        int xv = wsum[lane];
#pragma unroll
        for (int off = 1; off < 32; off <<= 1) {
            int u = __shfl_up_sync(0xFFFFFFFFu, xv, off);
            if (lane >= off) xv += u;
        }
        wsum[lane] = xv;
    }
    __syncthreads();
    const int base = (w > 0 ? wsum[w - 1] : 0) + (v - s);   // exclusive prefix
    if (m0v) g_cidx[b * Mm + 2 * t]     = base;
    if (m1v) g_cidx[b * Mm + 2 * t + 1] = base + m0v;
    if (t == 1023) g_nvalid[b] = wsum[31];
}

// ---------------------------------------------------------------------------
// Indicator row + Kc pad-band zeroing (runs after scan).
// ---------------------------------------------------------------------------
__global__ void fill_kernel()
{
    const int idx = blockIdx.x * 256 + threadIdx.x;   // 65536
    const int bh = idx >> 11, j = idx & 2047;
    const int nv = g_nvalid[bh >> 3];
    g_VTh[((size_t)bh * VTR + 64) * Mm + j] =
        __float2half_rn(j < nv ? 1.0f : 0.0f);
    if (j >= nv && j < ((nv + 63) & ~63)) {
        const uint4 z = {0u, 0u, 0u, 0u};
        uint4* kp = (uint4*)&g_Kh[((size_t)bh * Mm + j) * 16];
        kp[0] = z; kp[1] = z;
    }
}

// ---------------------------------------------------------------------------
// Weight conversion. 8 elements/thread.
// ---------------------------------------------------------------------------
__global__ void conv_w_kernel(const float* __restrict__ Wq,
                              const float* __restrict__ Wk,
                              const float* __restrict__ Wv)
{
    const int t = blockIdx.x * 256 + threadIdx.x;     // 49152
    const int j  = t >> 6;
    const int k0 = (t & 63) * 8;
    const float* src; int lds; int jj; float sc = 1.0f;
    if (j < 128)      { src = Wq; lds = 128; jj = j;       sc = QSCALE; }
    else if (j < 256) { src = Wk; lds = 128; jj = j - 128; }
    else              { src = Wv; lds = 512; jj = j - 256; }
    __align__(16) __half tmp[8];
#pragma unroll
    for (int i = 0; i < 8; i++)
        tmp[i] = __float2half_rn(src[(size_t)(k0 + i) * lds + jj] * sc);
    *(uint4*)&g_WT[j * Cc + k0] = *(uint4*)tmp;
}

// ---------------------------------------------------------------------------
// Kernel 1: HMMA QKV projection; K/V written at compacted key positions.
// ---------------------------------------------------------------------------
__global__ __launch_bounds__(256) void proj_kernel(
    const float* __restrict__ x, const int* __restrict__ mask,
    const float* __restrict__ bq, const float* __restrict__ bk,
    const float* __restrict__ bv)
{
    __shared__ __align__(16) char Ah[2][128 * 80];
    __shared__ __align__(16) char Bh[2][128 * 80];

    const int row0 = blockIdx.x * 128;
    const int col0 = blockIdx.y * 128;
    const int tid  = threadIdx.x;
    const int lane = tid & 31;
    const int wid  = tid >> 5;
    const int wm   = wid & 3;
    const int wn   = wid >> 2;

    const int rowi = lane & 7;
    const int rsel = (lane >> 4) & 1;
    const int csel = (lane >> 3) & 1;
    const int g    = lane >> 2;
    const int tig  = lane & 3;

    const uint32_t AhA = smem_u32(Ah);
    const uint32_t BhA = smem_u32(Bh);

    const int r0 = (tid * 2) >> 2, s0 = (tid * 2) & 3;
    const int r1 = (tid * 2 + 1) >> 2, s1 = (tid * 2 + 1) & 3;

    const float* xa0 = x + (size_t)(row0 + r0) * Cc + s0 * 8;
    const float* xa1 = x + (size_t)(row0 + r1) * Cc + s1 * 8;
    const __half* wb0 = g_WT + (size_t)(col0 + r0) * Cc + s0 * 8;
    const __half* wb1 = g_WT + (size_t)(col0 + r1) * Cc + s1 * 8;

    {
        float4 a00 = *(const float4*)xa0, a01 = *(const float4*)(xa0 + 4);
        float4 a10 = *(const float4*)xa1, a11 = *(const float4*)(xa1 + 4);
        *(uint4*)(Ah[0] + r0 * 80 + s0 * 16) = f8_to_h8(a00, a01);
        *(uint4*)(Ah[0] + r1 * 80 + s1 * 16) = f8_to_h8(a10, a11);
        *(uint4*)(Bh[0] + r0 * 80 + s0 * 16) = *(const uint4*)wb0;
        *(uint4*)(Bh[0] + r1 * 80 + s1 * 16) = *(const uint4*)wb1;
    }
    __syncthreads();

    float acc[2][8][4] = {};

    for (int it = 0; it < 16; it++) {
        float4 a00, a01, a10, a11;
        uint4 pb0, pb1;
        if (it < 15) {
            const int kn = (it + 1) * 32;
            a00 = *(const float4*)(xa0 + kn);
            a01 = *(const float4*)(xa0 + kn + 4);
            a10 = *(const float4*)(xa1 + kn);
            a11 = *(const float4*)(xa1 + kn + 4);
            pb0 = *(const uint4*)(wb0 + kn);
            pb1 = *(const uint4*)(wb1 + kn);
        }
        const uint32_t Ab = AhA + (uint32_t)(it & 1) * 10240u;
        const uint32_t Bc = BhA + (uint32_t)(it & 1) * 10240u;
#pragma unroll
        for (int ks = 0; ks < 2; ks++) {
            uint32_t qa[2][4];
#pragma unroll
            for (int mt = 0; mt < 2; mt++)
                ldm4(qa[mt], Ab + (wm * 32 + mt * 16 + rowi + csel * 8) * 80
                              + ks * 32 + rsel * 16);
#pragma unroll
            for (int nb = 0; nb < 4; nb++) {
                uint32_t kb[4];
                ldm4(kb, Bc + (wn * 64 + nb * 16 + rowi + rsel * 8) * 80
                           + ks * 32 + csel * 16);
                mma16816(acc[0][nb * 2],     qa[0], kb[0], kb[1]);
                mma16816(acc[0][nb * 2 + 1], qa[0], kb[2], kb[3]);
                mma16816(acc[1][nb * 2],     qa[1], kb[0], kb[1]);
                mma16816(acc[1][nb * 2 + 1], qa[1], kb[2], kb[3]);
            }
        }
        if (it < 15) {
            char* An = Ah[(it + 1) & 1];
            char* Bn = Bh[(it + 1) & 1];
            *(uint4*)(An + r0 * 80 + s0 * 16) = f8_to_h8(a00, a01);
            *(uint4*)(An + r1 * 80 + s1 * 16) = f8_to_h8(a10, a11);
            *(uint4*)(Bn + r0 * 80 + s0 * 16) = pb0;
            *(uint4*)(Bn + r1 * 80 + s1 * 16) = pb1;
            __syncthreads();
        }
    }

    // epilogue: Q direct; K/V to compacted key rows
    const int b    = row0 >> 11;
    const int mloc = (row0 & (Mm - 1)) + wm * 32;

#pragma unroll
    for (int mt = 0; mt < 2; mt++) {
        const int ma = mloc + mt * 16 + g;     // global m (row A)
        const int mb = ma + 8;                 // row B
        int mkA = 0, mkB = 0, cA = 0, cB = 0;
        if (col0 >= 128) {
            mkA = mask[b * Mm + ma];
            mkB = mask[b * Mm + mb];
            cA  = g_cidx[b * Mm + ma];
            cB  = g_cidx[b * Mm + mb];
        }
#pragma unroll
        for (int j = 0; j < 8; j++) {
            const int jg = col0 + wn * 64 + j * 8 + tig * 2;
            float c0 = acc[mt][j][0], c1 = acc[mt][j][1];
            float c2 = acc[mt][j][2], c3 = acc[mt][j][3];
            if (jg < 128) {
                const float b0 = bq[jg] * QSCALE, b1 = bq[jg + 1] * QSCALE;
                const int h = jg >> 4, dq = jg & 15;
                __half2 lo = __floats2half2_rn(c0 + b0, c1 + b1);
                __half2 hi = __floats2half2_rn(c2 + b0, c3 + b1);
                __half* base = &g_Qh[(((size_t)(b * Hh + h)) * Mm + ma) * 16 + dq];
                *(uint32_t*)base = *(uint32_t*)&lo;
                *(uint32_t*)(base + 8 * 16) = *(uint32_t*)&hi;
            } else if (jg < 256) {
                const int jj = jg - 128;
                const float b0 = bk[jj], b1 = bk[jj + 1];
                const int h = jj >> 4, dq = jj & 15;
                __half2 lo = __floats2half2_rn(c0 + b0, c1 + b1);
                __half2 hi = __floats2half2_rn(c2 + b0, c3 + b1);
                if (mkA)
                    *(uint32_t*)&g_Kh[(((size_t)(b * Hh + h)) * Mm + cA) * 16 + dq]
                        = *(uint32_t*)&lo;
                if (mkB)
                    *(uint32_t*)&g_Kh[(((size_t)(b * Hh + h)) * Mm + cB) * 16 + dq]
                        = *(uint32_t*)&hi;
            } else {
                const int jj = jg - 256;
                const float b0 = bv[jj], b1 = bv[jj + 1];
                const int h = jj >> 6, d = jj & 63;
                __half* rb = &g_VTh[(((size_t)(b * Hh + h)) * VTR + d) * Mm];
                if (mkA) {
                    rb[cA]      = __float2half_rn(c0 + b0);
                    rb[Mm + cA] = __float2half_rn(c1 + b1);
                }
                if (mkB) {
                    rb[cB]      = __float2half_rn(c2 + b0);
                    rb[Mm + cB] = __float2half_rn(c3 + b1);
                }
            }
        }
    }
}

// ---------------------------------------------------------------------------
// Kernel 2: HMMA fp16 flash attention over COMPACTED keys.
// ---------------------------------------------------------------------------
#define KB 3072
#define VB 10368    // 72 rows * 144B

__global__ __launch_bounds__(128, 4) void attn_kernel(
    const float* __restrict__ gamma, float* __restrict__ out)
{
    __shared__ __align__(16) char Qs[128 * 48];
    __shared__ __align__(16) char Ks[2][64 * 48];
    __shared__ __align__(16) char Vs[2][VTR * 144];

    const int tid  = threadIdx.x;
    const int w    = tid >> 5;
    const int lane = tid & 31;
    const int g    = lane >> 2;
    const int tig  = lane & 3;

    const int bh = blockIdx.x >> 4;
    const int mt = blockIdx.x & 15;
    const int b  = bh >> 3;
    const int h  = bh & 7;
    const int m0 = mt * 128;

    const int ntiles = (g_nvalid[b] + 63) >> 6;

    const uint32_t QsA = smem_u32(Qs);
    const uint32_t KsA = smem_u32(Ks);
    const uint32_t VsA = smem_u32(Vs);

    {
        const uint4* q4 = (const uint4*)(g_Qh + ((size_t)bh * Mm + m0 + tid) * 16);
        *(uint4*)(Qs + tid * 48)      = q4[0];
        *(uint4*)(Qs + tid * 48 + 16) = q4[1];
    }

    const __half* vsrc0 = g_VTh + ((size_t)bh * VTR + (tid >> 1)) * Mm + (tid & 1) * 32;
    const uint32_t vdst0 = VsA + (uint32_t)((tid >> 1) * 144 + (tid & 1) * 64);
    const __half* esrc0 = g_VTh + ((size_t)bh * VTR + 64 + (tid >> 3)) * Mm + (tid & 7) * 8;
    const uint32_t edst0 = VsA + (uint32_t)((64 + (tid >> 3)) * 144 + (tid & 7) * 16);
    const __half* ksrc0 = g_Kh + ((size_t)bh * Mm + tid) * 16;
    const uint32_t kdst0 = KsA + (uint32_t)(tid * 48);

    auto issue_tile = [&](int nt, int buf) {
        const int n0 = nt * 64;
        const __half* vs = vsrc0 + n0;
        const uint32_t vd = vdst0 + (uint32_t)buf * VB;
        CP16(vd,      vs);
        CP16(vd + 16, vs + 8);
        CP16(vd + 32, vs + 16);
        CP16(vd + 48, vs + 24);
        if (tid < 64) {
            const __half* ks = ksrc0 + (size_t)n0 * 16;
            const uint32_t kd = kdst0 + (uint32_t)buf * KB;
            CP16(kd,      ks);
            CP16(kd + 16, ks + 8);
            CP16(edst0 + (uint32_t)buf * VB, esrc0 + n0);
        }
    };

    if (ntiles > 0) issue_tile(0, 0);
    CP_COMMIT();
    __syncthreads();

    const int rsel = (lane >> 4) & 1;
    const int csel = (lane >> 3) & 1;
    const int rowi = (lane & 7);

    uint32_t qa[2][4];
#pragma unroll
    for (int mt2 = 0; mt2 < 2; mt2++)
        ldm4(qa[mt2], QsA + (w * 32 + mt2 * 16 + rowi + csel * 8) * 48 + rsel * 16);

    float o[2][8][4] = {};
    float oex[2][4] = {};

    const int knrow = rowi + rsel * 8;
    const int kcol  = csel * 16;
    const int ecol  = csel * 16;

    for (int nt = 0; nt < ntiles; nt++) {
        const int buf = nt & 1;
        if (nt + 1 < ntiles) {
            issue_tile(nt + 1, buf ^ 1);
            CP_COMMIT();
            CP_WAIT1();
        } else {
            CP_WAIT0();
        }
        __syncthreads();

        const uint32_t Kb = KsA + (uint32_t)buf * KB;
        const uint32_t Vb = VsA + (uint32_t)buf * VB;

#pragma unroll
        for (int kn = 0; kn < 4; kn++) {
            uint32_t kb[4];
            ldm4(kb, Kb + (kn * 16 + knrow) * 48 + kcol);

            uint32_t pa[2][4];
#pragma unroll
            for (int mt2 = 0; mt2 < 2; mt2++) {
                float c0[4] = {}, c1[4] = {};
                mma16816(c0, qa[mt2], kb[0], kb[1]);
                mma16816(c1, qa[mt2], kb[2], kb[3]);
                pa[mt2][0] = exp_relu_pack(c0[0], c0[1]);
                pa[mt2][1] = exp_relu_pack(c0[2], c0[3]);
                pa[mt2][2] = exp_relu_pack(c1[0], c1[1]);
                pa[mt2][3] = exp_relu_pack(c1[2], c1[3]);
            }

#pragma unroll
            for (int p = 0; p < 4; p++) {
                uint32_t vb[4];
                ldm4(vb, Vb + (p * 16 + knrow) * 144 + kn * 32 + kcol);
                mma16816(o[0][2 * p],     pa[0], vb[0], vb[1]);
                mma16816(o[0][2 * p + 1], pa[0], vb[2], vb[3]);
                mma16816(o[1][2 * p],     pa[1], vb[0], vb[1]);
                mma16816(o[1][2 * p + 1], pa[1], vb[2], vb[3]);
            }
            {
                uint32_t eb[2];
                ldm2(eb, Vb + (64 + rowi) * 144 + kn * 32 + ecol);
                mma16816(oex[0], pa[0], eb[0], eb[1]);
                mma16816(oex[1], pa[1], eb[0], eb[1]);
            }
        }
        __syncthreads();
    }

    const float gm = gamma[0];
    float inv[2][2];
#pragma unroll
    for (int mt2 = 0; mt2 < 2; mt2++) {
        const float d0 = __shfl_sync(0xFFFFFFFFu, oex[mt2][0], g << 2);
        const float d1 = __shfl_sync(0xFFFFFFFFu, oex[mt2][2], g << 2);
        inv[mt2][0] = gm / (d0 + 1e-12f);
        inv[mt2][1] = gm / (d1 + 1e-12f);
    }

#pragma unroll
    for (int mt2 = 0; mt2 < 2; mt2++) {
#pragma unroll
        for (int rh = 0; rh < 2; rh++) {
            const int m = m0 + w * 32 + mt2 * 16 + rh * 8 + g;
            float* op = out + ((size_t)b * Mm + m) * Cc + h * 64 + tig * 2;
            const float iv = inv[mt2][rh];
#pragma unroll
            for (int ntile = 0; ntile < 8; ntile++) {
                float2 v;
                v.x = o[mt2][ntile][rh * 2 + 0] * iv;
                v.y = o[mt2][ntile][rh * 2 + 1] * iv;
                *(float2*)(op + ntile * 8) = v;
            }
        }
    }
}

// ---------------------------------------------------------------------------
extern "C" void kernel_launch(void* const* d_in, const int* in_sizes, int n_in,
                              void* d_out, int out_size)
{
    const float* x     = (const float*)d_in[0];
    const int*   mask  = (const int*)  d_in[1];
    const float* Wq    = (const float*)d_in[2];
    const float* bq    = (const float*)d_in[3];
    const float* Wk    = (const float*)d_in[4];
    const float* bk    = (const float*)d_in[5];
    const float* Wv    = (const float*)d_in[6];
    const float* bv    = (const float*)d_in[7];
    const float* gamma = (const float*)d_in[8];
    float* out = (float*)d_out;

    scan_kernel<<<Bb, 1024>>>(mask);
    conv_w_kernel<<<192, 256>>>(Wq, Wk, Wv);
    fill_kernel<<<256, 256>>>();

    dim3 pg((Bb * Mm) / 128, 6);
    proj_kernel<<<pg, 256>>>(x, mask, bq, bk, bv);

    attn_kernel<<<BHt * (Mm / 128), 128>>>(gamma, out);
}

// round 13
// speedup vs baseline: 1.4316x; 1.1459x over previous
#include <cuda_runtime.h>
#include <cuda_fp16.h>
#include <cstdint>
#include <math.h>

#define Bb 4
#define Mm 2048
#define Cc 512
#define Hh 8
#define BHt 32
#define VTR 72                         // VT rows per bh: 64 V + 1 indicator + 7 zero pad

#define QSCALE 0.36067376022224085f    // 0.25 * log2(e)

// fp16 staging (compacted along keys)
__device__ __half g_xh[Bb * Mm * Cc];      // fp16 x
__device__ __half g_WT[768 * Cc];          // (j, k): Wq^T*QSCALE | Wk^T | Wv^T
__device__ __half g_Qh[BHt * Mm * 16];     // (bh, m, 16)  pre-scaled by QSCALE
__device__ __half g_Kh[BHt * Mm * 16];     // (bh, j, 16)  compacted keys
__device__ __half g_VTh[BHt * VTR * Mm];   // (bh, d, j)   compacted; d=64 indicator
__device__ int    g_cidx[Bb * Mm];
__device__ int    g_nvalid[Bb];

__device__ __forceinline__ uint32_t smem_u32(const void* p) {
    uint32_t a;
    asm("{ .reg .u64 t; cvta.to.shared.u64 t, %1; cvt.u32.u64 %0, t; }"
        : "=r"(a) : "l"(p));
    return a;
}
__device__ __forceinline__ void ldm4(uint32_t r[4], uint32_t addr) {
    asm volatile("ldmatrix.sync.aligned.m8n8.x4.shared.b16 {%0,%1,%2,%3}, [%4];"
                 : "=r"(r[0]), "=r"(r[1]), "=r"(r[2]), "=r"(r[3]) : "r"(addr));
}
__device__ __forceinline__ void ldm2(uint32_t r[2], uint32_t addr) {
    asm volatile("ldmatrix.sync.aligned.m8n8.x2.shared.b16 {%0,%1}, [%2];"
                 : "=r"(r[0]), "=r"(r[1]) : "r"(addr));
}
__device__ __forceinline__ void mma16816(float c[4], const uint32_t a[4],
                                         uint32_t b0, uint32_t b1) {
    asm volatile("mma.sync.aligned.m16n8k16.row.col.f32.f16.f16.f32 "
                 "{%0,%1,%2,%3}, {%4,%5,%6,%7}, {%8,%9}, {%0,%1,%2,%3};"
                 : "+f"(c[0]), "+f"(c[1]), "+f"(c[2]), "+f"(c[3])
                 : "r"(a[0]), "r"(a[1]), "r"(a[2]), "r"(a[3]), "r"(b0), "r"(b1));
}
__device__ __forceinline__ uint32_t exp_relu_pack(float lo, float hi) {
    uint32_t h, r;
    asm("cvt.rn.f16x2.f32 %0, %1, %2;" : "=r"(h) : "f"(hi), "f"(lo));
    asm("max.f16x2 %0, %0, %1;" : "+r"(h) : "r"(0u));
    asm("ex2.approx.f16x2 %0, %1;" : "=r"(r) : "r"(h));
    return r;
}
#define CP16(dst, src) \
    asm volatile("cp.async.ca.shared.global [%0], [%1], 16;" :: "r"(dst), "l"(src))
#define CP_COMMIT() asm volatile("cp.async.commit_group;")
#define CP_WAIT2()  asm volatile("cp.async.wait_group 2;")
#define CP_WAIT1()  asm volatile("cp.async.wait_group 1;")
#define CP_WAIT0()  asm volatile("cp.async.wait_group 0;")

__device__ __forceinline__ uint4 f8_to_h8(float4 a, float4 b) {
    __half2 h0 = __floats2half2_rn(a.x, a.y), h1 = __floats2half2_rn(a.z, a.w);
    __half2 h2 = __floats2half2_rn(b.x, b.y), h3 = __floats2half2_rn(b.z, b.w);
    uint4 u;
    u.x = *(uint32_t*)&h0; u.y = *(uint32_t*)&h1;
    u.z = *(uint32_t*)&h2; u.w = *(uint32_t*)&h3;
    return u;
}

// ---------------------------------------------------------------------------
// Order-preserving prefix scan of mask per batch.
// ---------------------------------------------------------------------------
__global__ __launch_bounds__(1024) void scan_kernel(const int* __restrict__ mask)
{
    const int b = blockIdx.x;
    const int t = threadIdx.x;
    const int m0v = mask[b * Mm + 2 * t];
    const int m1v = mask[b * Mm + 2 * t + 1];
    const int s = m0v + m1v;
    const int lane = t & 31, w = t >> 5;

    int v = s;
#pragma unroll
    for (int off = 1; off < 32; off <<= 1) {
        int u = __shfl_up_sync(0xFFFFFFFFu, v, off);
        if (lane >= off) v += u;
    }
    __shared__ int wsum[32];
    if (lane == 31) wsum[w] = v;
    __syncthreads();
    if (w == 0) {
        int xv = wsum[lane];
#pragma unroll
        for (int off = 1; off < 32; off <<= 1) {
            int u = __shfl_up_sync(0xFFFFFFFFu, xv, off);
            if (lane >= off) xv += u;
        }
        wsum[lane] = xv;
    }
    __syncthreads();
    const int base = (w > 0 ? wsum[w - 1] : 0) + (v - s);
    if (m0v) g_cidx[b * Mm + 2 * t]     = base;
    if (m1v) g_cidx[b * Mm + 2 * t + 1] = base + m0v;
    if (t == 1023) g_nvalid[b] = wsum[31];
}

// ---------------------------------------------------------------------------
// Indicator row + Kc pad-band zeroing (after scan).
// ---------------------------------------------------------------------------
__global__ void fill_kernel()
{
    const int idx = blockIdx.x * 256 + threadIdx.x;   // 65536
    const int bh = idx >> 11, j = idx & 2047;
    const int nv = g_nvalid[bh >> 3];
    g_VTh[((size_t)bh * VTR + 64) * Mm + j] =
        __float2half_rn(j < nv ? 1.0f : 0.0f);
    if (j >= nv && j < ((nv + 63) & ~63)) {
        const uint4 z = {0u, 0u, 0u, 0u};
        uint4* kp = (uint4*)&g_Kh[((size_t)bh * Mm + j) * 16];
        kp[0] = z; kp[1] = z;
    }
}

// ---------------------------------------------------------------------------
// Conversions: weights (transposed fp16) and x (fp16), 8 elems/thread.
// ---------------------------------------------------------------------------
__global__ void conv_kernel(const float* __restrict__ Wq,
                            const float* __restrict__ Wk,
                            const float* __restrict__ Wv,
                            const float* __restrict__ x)
{
    const int t = blockIdx.x * 256 + threadIdx.x;
    if (t < 49152) {
        const int j  = t >> 6;
        const int k0 = (t & 63) * 8;
        const float* src; int lds; int jj; float sc = 1.0f;
        if (j < 128)      { src = Wq; lds = 128; jj = j;       sc = QSCALE; }
        else if (j < 256) { src = Wk; lds = 128; jj = j - 128; }
        else              { src = Wv; lds = 512; jj = j - 256; }
        __align__(16) __half tmp[8];
#pragma unroll
        for (int i = 0; i < 8; i++)
            tmp[i] = __float2half_rn(src[(size_t)(k0 + i) * lds + jj] * sc);
        *(uint4*)&g_WT[j * Cc + k0] = *(uint4*)tmp;
    } else {
        const int i = (t - 49152) * 8;                // x: 4M elements
        float4 a = *(const float4*)&x[i];
        float4 b = *(const float4*)&x[i + 4];
        *(uint4*)&g_xh[i] = f8_to_h8(a, b);
    }
}

// ---------------------------------------------------------------------------
// Kernel 1: HMMA QKV projection. CTA tile 128x64, warp tile 32x32,
// 3-stage cp.async pipeline, K/V written at compacted positions.
// ---------------------------------------------------------------------------
#define PSTG 15360      // stage stride: A 128*80 + B 64*80

__global__ __launch_bounds__(256, 3) void proj_kernel(
    const int* __restrict__ mask,
    const float* __restrict__ bq, const float* __restrict__ bk,
    const float* __restrict__ bv)
{
    __shared__ __align__(16) char SM[3 * PSTG];

    const int row0 = blockIdx.x * 128;
    const int col0 = blockIdx.y * 64;
    const int tid  = threadIdx.x;
    const int lane = tid & 31;
    const int wid  = tid >> 5;
    const int wm   = wid & 3;        // warp m 0..3 (32 rows each)
    const int wn   = wid >> 2;       // warp n 0..1 (32 cols each)

    const int rowi = lane & 7;
    const int rsel = (lane >> 4) & 1;
    const int csel = (lane >> 3) & 1;
    const int g    = lane >> 2;
    const int tig  = lane & 3;

    const uint32_t SMA = smem_u32(SM);

    // load mapping: A 512 chunks (tid, tid+256), B 256 chunks (tid)
    const int ar0 = tid >> 2,        as0 = (tid & 3) * 16;          // A chunk tid
    const int ar1 = (tid + 256) >> 2, as1 = as0;                    // A chunk tid+256
    const int br_ = tid >> 2,        bs_ = (tid & 3) * 16;          // B chunk tid

    const __half* xaA = g_xh + (size_t)(row0 + ar0) * Cc + (as0 >> 1);
    const __half* xaB = g_xh + (size_t)(row0 + ar1) * Cc + (as1 >> 1);
    const __half* wbA = g_WT + (size_t)(col0 + br_) * Cc + (bs_ >> 1);

    auto issue_stage = [&](int it, int s) {
        const int k0 = it * 32;
        const uint32_t As = SMA + (uint32_t)s * PSTG;
        const uint32_t Bs = As + 10240u;
        CP16(As + (uint32_t)(ar0 * 80 + as0), xaA + k0);
        CP16(As + (uint32_t)(ar1 * 80 + as1), xaB + k0);
        CP16(Bs + (uint32_t)(br_ * 80 + bs_), wbA + k0);
    };

    issue_stage(0, 0); CP_COMMIT();
    issue_stage(1, 1); CP_COMMIT();

    float acc[2][4][4] = {};

    for (int it = 0; it < 16; it++) {
        if (it + 2 < 16) issue_stage(it + 2, (it + 2) % 3);
        CP_COMMIT();                    // empty group ok at tail
        CP_WAIT2();                     // stage `it` complete
        __syncthreads();

        const uint32_t As = SMA + (uint32_t)(it % 3) * PSTG;
        const uint32_t Bs = As + 10240u;
#pragma unroll
        for (int ks = 0; ks < 2; ks++) {
            uint32_t qa[2][4];
#pragma unroll
            for (int mt = 0; mt < 2; mt++)
                ldm4(qa[mt], As + (wm * 32 + mt * 16 + rowi + csel * 8) * 80
                              + ks * 32 + rsel * 16);
#pragma unroll
            for (int nb = 0; nb < 2; nb++) {
                uint32_t kb[4];
                ldm4(kb, Bs + (wn * 32 + nb * 16 + rowi + rsel * 8) * 80
                           + ks * 32 + csel * 16);
                mma16816(acc[0][nb * 2],     qa[0], kb[0], kb[1]);
                mma16816(acc[0][nb * 2 + 1], qa[0], kb[2], kb[3]);
                mma16816(acc[1][nb * 2],     qa[1], kb[0], kb[1]);
                mma16816(acc[1][nb * 2 + 1], qa[1], kb[2], kb[3]);
            }
        }
        __syncthreads();
    }

    // epilogue: Q direct; K/V to compacted key rows
    const int b    = row0 >> 11;
    const int mloc = (row0 & (Mm - 1)) + wm * 32;

#pragma unroll
    for (int mt = 0; mt < 2; mt++) {
        const int ma = mloc + mt * 16 + g;
        const int mb = ma + 8;
        int mkA = 0, mkB = 0, cA = 0, cB = 0;
        if (col0 >= 128) {
            mkA = mask[b * Mm + ma];
            mkB = mask[b * Mm + mb];
            cA  = g_cidx[b * Mm + ma];
            cB  = g_cidx[b * Mm + mb];
        }
#pragma unroll
        for (int j = 0; j < 4; j++) {
            const int jg = col0 + wn * 32 + j * 8 + tig * 2;
            float c0 = acc[mt][j][0], c1 = acc[mt][j][1];
            float c2 = acc[mt][j][2], c3 = acc[mt][j][3];
            if (jg < 128) {
                const float b0 = bq[jg] * QSCALE, b1 = bq[jg + 1] * QSCALE;
                const int h = jg >> 4, dq = jg & 15;
                __half2 lo = __floats2half2_rn(c0 + b0, c1 + b1);
                __half2 hi = __floats2half2_rn(c2 + b0, c3 + b1);
                __half* base = &g_Qh[(((size_t)(b * Hh + h)) * Mm + ma) * 16 + dq];
                *(uint32_t*)base = *(uint32_t*)&lo;
                *(uint32_t*)(base + 8 * 16) = *(uint32_t*)&hi;
            } else if (jg < 256) {
                const int jj = jg - 128;
                const float b0 = bk[jj], b1 = bk[jj + 1];
                const int h = jj >> 4, dq = jj & 15;
                __half2 lo = __floats2half2_rn(c0 + b0, c1 + b1);
                __half2 hi = __floats2half2_rn(c2 + b0, c3 + b1);
                if (mkA)
                    *(uint32_t*)&g_Kh[(((size_t)(b * Hh + h)) * Mm + cA) * 16 + dq]
                        = *(uint32_t*)&lo;
                if (mkB)
                    *(uint32_t*)&g_Kh[(((size_t)(b * Hh + h)) * Mm + cB) * 16 + dq]
                        = *(uint32_t*)&hi;
            } else {
                const int jj = jg - 256;
                const float b0 = bv[jj], b1 = bv[jj + 1];
                const int h = jj >> 6, d = jj & 63;
                __half* rb = &g_VTh[(((size_t)(b * Hh + h)) * VTR + d) * Mm];
                if (mkA) {
                    rb[cA]      = __float2half_rn(c0 + b0);
                    rb[Mm + cA] = __float2half_rn(c1 + b1);
                }
                if (mkB) {
                    rb[cB]      = __float2half_rn(c2 + b0);
                    rb[Mm + cB] = __float2half_rn(c3 + b1);
                }
            }
        }
    }
}

// ---------------------------------------------------------------------------
// Kernel 2: HMMA fp16 flash attention over COMPACTED keys (unchanged R12).
// ---------------------------------------------------------------------------
#define KB 3072
#define VB 10368

__global__ __launch_bounds__(128, 4) void attn_kernel(
    const float* __restrict__ gamma, float* __restrict__ out)
{
    __shared__ __align__(16) char Qs[128 * 48];
    __shared__ __align__(16) char Ks[2][64 * 48];
    __shared__ __align__(16) char Vs[2][VTR * 144];

    const int tid  = threadIdx.x;
    const int w    = tid >> 5;
    const int lane = tid & 31;
    const int g    = lane >> 2;
    const int tig  = lane & 3;

    const int bh = blockIdx.x >> 4;
    const int mt = blockIdx.x & 15;
    const int b  = bh >> 3;
    const int h  = bh & 7;
    const int m0 = mt * 128;

    const int ntiles = (g_nvalid[b] + 63) >> 6;

    const uint32_t QsA = smem_u32(Qs);
    const uint32_t KsA = smem_u32(Ks);
    const uint32_t VsA = smem_u32(Vs);

    {
        const uint4* q4 = (const uint4*)(g_Qh + ((size_t)bh * Mm + m0 + tid) * 16);
        *(uint4*)(Qs + tid * 48)      = q4[0];
        *(uint4*)(Qs + tid * 48 + 16) = q4[1];
    }

    const __half* vsrc0 = g_VTh + ((size_t)bh * VTR + (tid >> 1)) * Mm + (tid & 1) * 32;
    const uint32_t vdst0 = VsA + (uint32_t)((tid >> 1) * 144 + (tid & 1) * 64);
    const __half* esrc0 = g_VTh + ((size_t)bh * VTR + 64 + (tid >> 3)) * Mm + (tid & 7) * 8;
    const uint32_t edst0 = VsA + (uint32_t)((64 + (tid >> 3)) * 144 + (tid & 7) * 16);
    const __half* ksrc0 = g_Kh + ((size_t)bh * Mm + tid) * 16;
    const uint32_t kdst0 = KsA + (uint32_t)(tid * 48);

    auto issue_tile = [&](int nt, int buf) {
        const int n0 = nt * 64;
        const __half* vs = vsrc0 + n0;
        const uint32_t vd = vdst0 + (uint32_t)buf * VB;
        CP16(vd,      vs);
        CP16(vd + 16, vs + 8);
        CP16(vd + 32, vs + 16);
        CP16(vd + 48, vs + 24);
        if (tid < 64) {
            const __half* ks = ksrc0 + (size_t)n0 * 16;
            const uint32_t kd = kdst0 + (uint32_t)buf * KB;
            CP16(kd,      ks);
            CP16(kd + 16, ks + 8);
            CP16(edst0 + (uint32_t)buf * VB, esrc0 + n0);
        }
    };

    if (ntiles > 0) issue_tile(0, 0);
    CP_COMMIT();
    __syncthreads();

    const int rsel = (lane >> 4) & 1;
    const int csel = (lane >> 3) & 1;
    const int rowi = (lane & 7);

    uint32_t qa[2][4];
#pragma unroll
    for (int mt2 = 0; mt2 < 2; mt2++)
        ldm4(qa[mt2], QsA + (w * 32 + mt2 * 16 + rowi + csel * 8) * 48 + rsel * 16);

    float o[2][8][4] = {};
    float oex[2][4] = {};

    const int knrow = rowi + rsel * 8;
    const int kcol  = csel * 16;
    const int ecol  = csel * 16;

    for (int nt = 0; nt < ntiles; nt++) {
        const int buf = nt & 1;
        if (nt + 1 < ntiles) {
            issue_tile(nt + 1, buf ^ 1);
            CP_COMMIT();
            CP_WAIT1();
        } else {
            CP_WAIT0();
        }
        __syncthreads();

        const uint32_t Kb = KsA + (uint32_t)buf * KB;
        const uint32_t Vb = VsA + (uint32_t)buf * VB;

#pragma unroll
        for (int kn = 0; kn < 4; kn++) {
            uint32_t kb[4];
            ldm4(kb, Kb + (kn * 16 + knrow) * 48 + kcol);

            uint32_t pa[2][4];
#pragma unroll
            for (int mt2 = 0; mt2 < 2; mt2++) {
                float c0[4] = {}, c1[4] = {};
                mma16816(c0, qa[mt2], kb[0], kb[1]);
                mma16816(c1, qa[mt2], kb[2], kb[3]);
                pa[mt2][0] = exp_relu_pack(c0[0], c0[1]);
                pa[mt2][1] = exp_relu_pack(c0[2], c0[3]);
                pa[mt2][2] = exp_relu_pack(c1[0], c1[1]);
                pa[mt2][3] = exp_relu_pack(c1[2], c1[3]);
            }

#pragma unroll
            for (int p = 0; p < 4; p++) {
                uint32_t vb[4];
                ldm4(vb, Vb + (p * 16 + knrow) * 144 + kn * 32 + kcol);
                mma16816(o[0][2 * p],     pa[0], vb[0], vb[1]);
                mma16816(o[0][2 * p + 1], pa[0], vb[2], vb[3]);
                mma16816(o[1][2 * p],     pa[1], vb[0], vb[1]);
                mma16816(o[1][2 * p + 1], pa[1], vb[2], vb[3]);
            }
            {
                uint32_t eb[2];
                ldm2(eb, Vb + (64 + rowi) * 144 + kn * 32 + ecol);
                mma16816(oex[0], pa[0], eb[0], eb[1]);
                mma16816(oex[1], pa[1], eb[0], eb[1]);
            }
        }
        __syncthreads();
    }

    const float gm = gamma[0];
    float inv[2][2];
#pragma unroll
    for (int mt2 = 0; mt2 < 2; mt2++) {
        const float d0 = __shfl_sync(0xFFFFFFFFu, oex[mt2][0], g << 2);
        const float d1 = __shfl_sync(0xFFFFFFFFu, oex[mt2][2], g << 2);
        inv[mt2][0] = gm / (d0 + 1e-12f);
        inv[mt2][1] = gm / (d1 + 1e-12f);
    }

#pragma unroll
    for (int mt2 = 0; mt2 < 2; mt2++) {
#pragma unroll
        for (int rh = 0; rh < 2; rh++) {
            const int m = m0 + w * 32 + mt2 * 16 + rh * 8 + g;
            float* op = out + ((size_t)b * Mm + m) * Cc + h * 64 + tig * 2;
            const float iv = inv[mt2][rh];
#pragma unroll
            for (int ntile = 0; ntile < 8; ntile++) {
                float2 v;
                v.x = o[mt2][ntile][rh * 2 + 0] * iv;
                v.y = o[mt2][ntile][rh * 2 + 1] * iv;
                *(float2*)(op + ntile * 8) = v;
            }
        }
    }
}

// ---------------------------------------------------------------------------
extern "C" void kernel_launch(void* const* d_in, const int* in_sizes, int n_in,
                              void* d_out, int out_size)
{
    const float* x     = (const float*)d_in[0];
    const int*   mask  = (const int*)  d_in[1];
    const float* Wq    = (const float*)d_in[2];
    const float* bq    = (const float*)d_in[3];
    const float* Wk    = (const float*)d_in[4];
    const float* bk    = (const float*)d_in[5];
    const float* Wv    = (const float*)d_in[6];
    const float* bv    = (const float*)d_in[7];
    const float* gamma = (const float*)d_in[8];
    float* out = (float*)d_out;

    scan_kernel<<<Bb, 1024>>>(mask);
    conv_kernel<<<2240, 256>>>(Wq, Wk, Wv, x);
    fill_kernel<<<256, 256>>>();

    dim3 pg((Bb * Mm) / 128, 12);
    proj_kernel<<<pg, 256>>>(mask, bq, bk, bv);

    attn_kernel<<<BHt * (Mm / 128), 128>>>(gamma, out);
}

// round 14
// speedup vs baseline: 1.4752x; 1.0305x over previous
#include <cuda_runtime.h>
#include <cuda_fp16.h>
#include <cstdint>
#include <math.h>

#define Bb 4
#define Mm 2048
#define Cc 512
#define Hh 8
#define BHt 32
#define VTR 72                         // VT rows per bh: 64 V + 1 indicator + 7 zero pad

#define QSCALE 0.36067376022224085f    // 0.25 * log2(e)

// fp16 staging (compacted along keys)
__device__ __half g_xh[Bb * Mm * Cc];      // fp16 x
__device__ __half g_WT[768 * Cc];          // (j, k): Wq^T*QSCALE | Wk^T | Wv^T
__device__ __half g_Qh[BHt * Mm * 16];     // (bh, m, 16)  pre-scaled by QSCALE
__device__ __half g_Kh[BHt * Mm * 16];     // (bh, j, 16)  compacted keys
__device__ __half g_VTh[BHt * VTR * Mm];   // (bh, d, j)   compacted; d=64 indicator
__device__ int    g_cidx[Bb * Mm];
__device__ int    g_nvalid[Bb];

__device__ __forceinline__ uint32_t smem_u32(const void* p) {
    uint32_t a;
    asm("{ .reg .u64 t; cvta.to.shared.u64 t, %1; cvt.u32.u64 %0, t; }"
        : "=r"(a) : "l"(p));
    return a;
}
__device__ __forceinline__ void ldm4(uint32_t r[4], uint32_t addr) {
    asm volatile("ldmatrix.sync.aligned.m8n8.x4.shared.b16 {%0,%1,%2,%3}, [%4];"
                 : "=r"(r[0]), "=r"(r[1]), "=r"(r[2]), "=r"(r[3]) : "r"(addr));
}
__device__ __forceinline__ void ldm2(uint32_t r[2], uint32_t addr) {
    asm volatile("ldmatrix.sync.aligned.m8n8.x2.shared.b16 {%0,%1}, [%2];"
                 : "=r"(r[0]), "=r"(r[1]) : "r"(addr));
}
__device__ __forceinline__ void mma16816(float c[4], const uint32_t a[4],
                                         uint32_t b0, uint32_t b1) {
    asm volatile("mma.sync.aligned.m16n8k16.row.col.f32.f16.f16.f32 "
                 "{%0,%1,%2,%3}, {%4,%5,%6,%7}, {%8,%9}, {%0,%1,%2,%3};"
                 : "+f"(c[0]), "+f"(c[1]), "+f"(c[2]), "+f"(c[3])
                 : "r"(a[0]), "r"(a[1]), "r"(a[2]), "r"(a[3]), "r"(b0), "r"(b1));
}
__device__ __forceinline__ uint32_t exp_relu_pack(float lo, float hi) {
    uint32_t h, r;
    asm("cvt.rn.f16x2.f32 %0, %1, %2;" : "=r"(h) : "f"(hi), "f"(lo));
    asm("max.f16x2 %0, %0, %1;" : "+r"(h) : "r"(0u));
    asm("ex2.approx.f16x2 %0, %1;" : "=r"(r) : "r"(h));
    return r;
}
#define CP16(dst, src) \
    asm volatile("cp.async.ca.shared.global [%0], [%1], 16;" :: "r"(dst), "l"(src))
#define CP_COMMIT() asm volatile("cp.async.commit_group;")
#define CP_WAIT2()  asm volatile("cp.async.wait_group 2;")
#define CP_WAIT1()  asm volatile("cp.async.wait_group 1;")
#define CP_WAIT0()  asm volatile("cp.async.wait_group 0;")

__device__ __forceinline__ uint4 f8_to_h8(float4 a, float4 b) {
    __half2 h0 = __floats2half2_rn(a.x, a.y), h1 = __floats2half2_rn(a.z, a.w);
    __half2 h2 = __floats2half2_rn(b.x, b.y), h3 = __floats2half2_rn(b.z, b.w);
    uint4 u;
    u.x = *(uint32_t*)&h0; u.y = *(uint32_t*)&h1;
    u.z = *(uint32_t*)&h2; u.w = *(uint32_t*)&h3;
    return u;
}

// ---------------------------------------------------------------------------
// Prefix scan of mask per batch + indicator row + K pad-band zeroing.
// ---------------------------------------------------------------------------
__global__ __launch_bounds__(1024) void scan_kernel(const int* __restrict__ mask)
{
    const int b = blockIdx.x;
    const int t = threadIdx.x;
    const int m0v = mask[b * Mm + 2 * t];
    const int m1v = mask[b * Mm + 2 * t + 1];
    const int s = m0v + m1v;
    const int lane = t & 31, w = t >> 5;

    int v = s;
#pragma unroll
    for (int off = 1; off < 32; off <<= 1) {
        int u = __shfl_up_sync(0xFFFFFFFFu, v, off);
        if (lane >= off) v += u;
    }
    __shared__ int wsum[32];
    if (lane == 31) wsum[w] = v;
    __syncthreads();
    if (w == 0) {
        int xv = wsum[lane];
#pragma unroll
        for (int off = 1; off < 32; off <<= 1) {
            int u = __shfl_up_sync(0xFFFFFFFFu, xv, off);
            if (lane >= off) xv += u;
        }
        wsum[lane] = xv;
    }
    __syncthreads();
    const int base = (w > 0 ? wsum[w - 1] : 0) + (v - s);
    if (m0v) g_cidx[b * Mm + 2 * t]     = base;
    if (m1v) g_cidx[b * Mm + 2 * t + 1] = base + m0v;

    const int nv = wsum[31];
    if (t == 0) g_nvalid[b] = nv;

    // indicator rows for this batch's 8 heads (fp16, 2048 each)
    const __half one  = __float2half_rn(1.0f);
    const __half zero = __float2half_rn(0.0f);
#pragma unroll
    for (int h = 0; h < Hh; h++) {
        __half* row = &g_VTh[(((size_t)(b * Hh + h)) * VTR + 64) * Mm];
        const int j0 = t, j1 = t + 1024;
        row[j0] = (j0 < nv) ? one : zero;
        row[j1] = (j1 < nv) ? one : zero;
    }
    // zero K pad band [nv, align64(nv)) for 8 heads
    const int padn = ((nv + 63) & ~63) - nv;       // 0..63
    if (t < padn * Hh) {
        const int h = t / padn;
        const int j = nv + (t % padn);
        const uint4 z = {0u, 0u, 0u, 0u};
        uint4* kp = (uint4*)&g_Kh[(((size_t)(b * Hh + h)) * Mm + j) * 16];
        kp[0] = z; kp[1] = z;
    }
}

// ---------------------------------------------------------------------------
// Conversions: weights (transposed fp16) and x (fp16), 8 elems/thread.
// ---------------------------------------------------------------------------
__global__ void conv_kernel(const float* __restrict__ Wq,
                            const float* __restrict__ Wk,
                            const float* __restrict__ Wv,
                            const float* __restrict__ x)
{
    const int t = blockIdx.x * 256 + threadIdx.x;
    if (t < 49152) {
        const int j  = t >> 6;
        const int k0 = (t & 63) * 8;
        const float* src; int lds; int jj; float sc = 1.0f;
        if (j < 128)      { src = Wq; lds = 128; jj = j;       sc = QSCALE; }
        else if (j < 256) { src = Wk; lds = 128; jj = j - 128; }
        else              { src = Wv; lds = 512; jj = j - 256; }
        __align__(16) __half tmp[8];
#pragma unroll
        for (int i = 0; i < 8; i++)
            tmp[i] = __float2half_rn(src[(size_t)(k0 + i) * lds + jj] * sc);
        *(uint4*)&g_WT[j * Cc + k0] = *(uint4*)tmp;
    } else {
        const int i = (t - 49152) * 8;
        float4 a = *(const float4*)&x[i];
        float4 b = *(const float4*)&x[i + 4];
        *(uint4*)&g_xh[i] = f8_to_h8(a, b);
    }
}

// ---------------------------------------------------------------------------
// Kernel 1: HMMA QKV projection. CTA tile 128x64, warp tile 32x32,
// 4-stage cp.async pipeline, ONE barrier per k-iteration.
// ---------------------------------------------------------------------------
#define PSTG 15360      // stage stride: A 128*80 + B 64*80
#define PNST 4

__global__ __launch_bounds__(256, 3) void proj_kernel(
    const int* __restrict__ mask,
    const float* __restrict__ bq, const float* __restrict__ bk,
    const float* __restrict__ bv)
{
    extern __shared__ __align__(16) char SM[];   // PNST * PSTG

    const int row0 = blockIdx.x * 128;
    const int col0 = blockIdx.y * 64;
    const int tid  = threadIdx.x;
    const int lane = tid & 31;
    const int wid  = tid >> 5;
    const int wm   = wid & 3;
    const int wn   = wid >> 2;

    const int rowi = lane & 7;
    const int rsel = (lane >> 4) & 1;
    const int csel = (lane >> 3) & 1;
    const int g    = lane >> 2;
    const int tig  = lane & 3;

    const uint32_t SMA = smem_u32(SM);

    const int ar0 = tid >> 2,         as0 = (tid & 3) * 16;
    const int ar1 = (tid + 256) >> 2, as1 = as0;
    const int br_ = tid >> 2,         bs_ = (tid & 3) * 16;

    const __half* xaA = g_xh + (size_t)(row0 + ar0) * Cc + (as0 >> 1);
    const __half* xaB = g_xh + (size_t)(row0 + ar1) * Cc + (as1 >> 1);
    const __half* wbA = g_WT + (size_t)(col0 + br_) * Cc + (bs_ >> 1);

    auto issue_stage = [&](int it, int s) {
        const int k0 = it * 32;
        const uint32_t As = SMA + (uint32_t)s * PSTG;
        const uint32_t Bs = As + 10240u;
        CP16(As + (uint32_t)(ar0 * 80 + as0), xaA + k0);
        CP16(As + (uint32_t)(ar1 * 80 + as1), xaB + k0);
        CP16(Bs + (uint32_t)(br_ * 80 + bs_), wbA + k0);
    };

    issue_stage(0, 0); CP_COMMIT();
    issue_stage(1, 1); CP_COMMIT();
    issue_stage(2, 2); CP_COMMIT();

    float acc[2][4][4] = {};

    for (int it = 0; it < 16; it++) {
        CP_WAIT2();                    // stage `it` complete (3 groups in flight)
        __syncthreads();               // all reads of stage (it+3)%4 done; data visible
        if (it + 3 < 16) issue_stage(it + 3, (it + 3) & 3);
        CP_COMMIT();                   // exactly one group per iteration

        const uint32_t As = SMA + (uint32_t)(it & 3) * PSTG;
        const uint32_t Bs = As + 10240u;
#pragma unroll
        for (int ks = 0; ks < 2; ks++) {
            uint32_t qa[2][4];
#pragma unroll
            for (int mt = 0; mt < 2; mt++)
                ldm4(qa[mt], As + (wm * 32 + mt * 16 + rowi + csel * 8) * 80
                              + ks * 32 + rsel * 16);
#pragma unroll
            for (int nb = 0; nb < 2; nb++) {
                uint32_t kb[4];
                ldm4(kb, Bs + (wn * 32 + nb * 16 + rowi + rsel * 8) * 80
                           + ks * 32 + csel * 16);
                mma16816(acc[0][nb * 2],     qa[0], kb[0], kb[1]);
                mma16816(acc[0][nb * 2 + 1], qa[0], kb[2], kb[3]);
                mma16816(acc[1][nb * 2],     qa[1], kb[0], kb[1]);
                mma16816(acc[1][nb * 2 + 1], qa[1], kb[2], kb[3]);
            }
        }
    }

    // epilogue: Q direct; K/V to compacted key rows
    const int b    = row0 >> 11;
    const int mloc = (row0 & (Mm - 1)) + wm * 32;

#pragma unroll
    for (int mt = 0; mt < 2; mt++) {
        const int ma = mloc + mt * 16 + g;
        const int mb = ma + 8;
        int mkA = 0, mkB = 0, cA = 0, cB = 0;
        if (col0 >= 128) {
            mkA = mask[b * Mm + ma];
            mkB = mask[b * Mm + mb];
            cA  = g_cidx[b * Mm + ma];
            cB  = g_cidx[b * Mm + mb];
        }
#pragma unroll
        for (int j = 0; j < 4; j++) {
            const int jg = col0 + wn * 32 + j * 8 + tig * 2;
            float c0 = acc[mt][j][0], c1 = acc[mt][j][1];
            float c2 = acc[mt][j][2], c3 = acc[mt][j][3];
            if (jg < 128) {
                const float b0 = bq[jg] * QSCALE, b1 = bq[jg + 1] * QSCALE;
                const int h = jg >> 4, dq = jg & 15;
                __half2 lo = __floats2half2_rn(c0 + b0, c1 + b1);
                __half2 hi = __floats2half2_rn(c2 + b0, c3 + b1);
                __half* base = &g_Qh[(((size_t)(b * Hh + h)) * Mm + ma) * 16 + dq];
                *(uint32_t*)base = *(uint32_t*)&lo;
                *(uint32_t*)(base + 8 * 16) = *(uint32_t*)&hi;
            } else if (jg < 256) {
                const int jj = jg - 128;
                const float b0 = bk[jj], b1 = bk[jj + 1];
                const int h = jj >> 4, dq = jj & 15;
                __half2 lo = __floats2half2_rn(c0 + b0, c1 + b1);
                __half2 hi = __floats2half2_rn(c2 + b0, c3 + b1);
                if (mkA)
                    *(uint32_t*)&g_Kh[(((size_t)(b * Hh + h)) * Mm + cA) * 16 + dq]
                        = *(uint32_t*)&lo;
                if (mkB)
                    *(uint32_t*)&g_Kh[(((size_t)(b * Hh + h)) * Mm + cB) * 16 + dq]
                        = *(uint32_t*)&hi;
            } else {
                const int jj = jg - 256;
                const float b0 = bv[jj], b1 = bv[jj + 1];
                const int h = jj >> 6, d = jj & 63;
                __half* rb = &g_VTh[(((size_t)(b * Hh + h)) * VTR + d) * Mm];
                if (mkA) {
                    rb[cA]      = __float2half_rn(c0 + b0);
                    rb[Mm + cA] = __float2half_rn(c1 + b1);
                }
                if (mkB) {
                    rb[cB]      = __float2half_rn(c2 + b0);
                    rb[Mm + cB] = __float2half_rn(c3 + b1);
                }
            }
        }
    }
}

// ---------------------------------------------------------------------------
// Kernel 2: HMMA fp16 flash attention over COMPACTED keys (unchanged).
// ---------------------------------------------------------------------------
#define KB 3072
#define VB 10368

__global__ __launch_bounds__(128, 4) void attn_kernel(
    const float* __restrict__ gamma, float* __restrict__ out)
{
    __shared__ __align__(16) char Qs[128 * 48];
    __shared__ __align__(16) char Ks[2][64 * 48];
    __shared__ __align__(16) char Vs[2][VTR * 144];

    const int tid  = threadIdx.x;
    const int w    = tid >> 5;
    const int lane = tid & 31;
    const int g    = lane >> 2;
    const int tig  = lane & 3;

    const int bh = blockIdx.x >> 4;
    const int mt = blockIdx.x & 15;
    const int b  = bh >> 3;
    const int h  = bh & 7;
    const int m0 = mt * 128;

    const int ntiles = (g_nvalid[b] + 63) >> 6;

    const uint32_t QsA = smem_u32(Qs);
    const uint32_t KsA = smem_u32(Ks);
    const uint32_t VsA = smem_u32(Vs);

    {
        const uint4* q4 = (const uint4*)(g_Qh + ((size_t)bh * Mm + m0 + tid) * 16);
        *(uint4*)(Qs + tid * 48)      = q4[0];
        *(uint4*)(Qs + tid * 48 + 16) = q4[1];
    }

    const __half* vsrc0 = g_VTh + ((size_t)bh * VTR + (tid >> 1)) * Mm + (tid & 1) * 32;
    const uint32_t vdst0 = VsA + (uint32_t)((tid >> 1) * 144 + (tid & 1) * 64);
    const __half* esrc0 = g_VTh + ((size_t)bh * VTR + 64 + (tid >> 3)) * Mm + (tid & 7) * 8;
    const uint32_t edst0 = VsA + (uint32_t)((64 + (tid >> 3)) * 144 + (tid & 7) * 16);
    const __half* ksrc0 = g_Kh + ((size_t)bh * Mm + tid) * 16;
    const uint32_t kdst0 = KsA + (uint32_t)(tid * 48);

    auto issue_tile = [&](int nt, int buf) {
        const int n0 = nt * 64;
        const __half* vs = vsrc0 + n0;
        const uint32_t vd = vdst0 + (uint32_t)buf * VB;
        CP16(vd,      vs);
        CP16(vd + 16, vs + 8);
        CP16(vd + 32, vs + 16);
        CP16(vd + 48, vs + 24);
        if (tid < 64) {
            const __half* ks = ksrc0 + (size_t)n0 * 16;
            const uint32_t kd = kdst0 + (uint32_t)buf * KB;
            CP16(kd,      ks);
            CP16(kd + 16, ks + 8);
            CP16(edst0 + (uint32_t)buf * VB, esrc0 + n0);
        }
    };

    if (ntiles > 0) issue_tile(0, 0);
    CP_COMMIT();
    __syncthreads();

    const int rsel = (lane >> 4) & 1;
    const int csel = (lane >> 3) & 1;
    const int rowi = (lane & 7);

    uint32_t qa[2][4];
#pragma unroll
    for (int mt2 = 0; mt2 < 2; mt2++)
        ldm4(qa[mt2], QsA + (w * 32 + mt2 * 16 + rowi + csel * 8) * 48 + rsel * 16);

    float o[2][8][4] = {};
    float oex[2][4] = {};

    const int knrow = rowi + rsel * 8;
    const int kcol  = csel * 16;
    const int ecol  = csel * 16;

    for (int nt = 0; nt < ntiles; nt++) {
        const int buf = nt & 1;
        if (nt + 1 < ntiles) {
            issue_tile(nt + 1, buf ^ 1);
            CP_COMMIT();
            CP_WAIT1();
        } else {
            CP_WAIT0();
        }
        __syncthreads();

        const uint32_t Kb = KsA + (uint32_t)buf * KB;
        const uint32_t Vb = VsA + (uint32_t)buf * VB;

#pragma unroll
        for (int kn = 0; kn < 4; kn++) {
            uint32_t kb[4];
            ldm4(kb, Kb + (kn * 16 + knrow) * 48 + kcol);

            uint32_t pa[2][4];
#pragma unroll
            for (int mt2 = 0; mt2 < 2; mt2++) {
                float c0[4] = {}, c1[4] = {};
                mma16816(c0, qa[mt2], kb[0], kb[1]);
                mma16816(c1, qa[mt2], kb[2], kb[3]);
                pa[mt2][0] = exp_relu_pack(c0[0], c0[1]);
                pa[mt2][1] = exp_relu_pack(c0[2], c0[3]);
                pa[mt2][2] = exp_relu_pack(c1[0], c1[1]);
                pa[mt2][3] = exp_relu_pack(c1[2], c1[3]);
            }

#pragma unroll
            for (int p = 0; p < 4; p++) {
                uint32_t vb[4];
                ldm4(vb, Vb + (p * 16 + knrow) * 144 + kn * 32 + kcol);
                mma16816(o[0][2 * p],     pa[0], vb[0], vb[1]);
                mma16816(o[0][2 * p + 1], pa[0], vb[2], vb[3]);
                mma16816(o[1][2 * p],     pa[1], vb[0], vb[1]);
                mma16816(o[1][2 * p + 1], pa[1], vb[2], vb[3]);
            }
            {
                uint32_t eb[2];
                ldm2(eb, Vb + (64 + rowi) * 144 + kn * 32 + ecol);
                mma16816(oex[0], pa[0], eb[0], eb[1]);
                mma16816(oex[1], pa[1], eb[0], eb[1]);
            }
        }
        __syncthreads();
    }

    const float gm = gamma[0];
    float inv[2][2];
#pragma unroll
    for (int mt2 = 0; mt2 < 2; mt2++) {
        const float d0 = __shfl_sync(0xFFFFFFFFu, oex[mt2][0], g << 2);
        const float d1 = __shfl_sync(0xFFFFFFFFu, oex[mt2][2], g << 2);
        inv[mt2][0] = gm / (d0 + 1e-12f);
        inv[mt2][1] = gm / (d1 + 1e-12f);
    }

#pragma unroll
    for (int mt2 = 0; mt2 < 2; mt2++) {
#pragma unroll
        for (int rh = 0; rh < 2; rh++) {
            const int m = m0 + w * 32 + mt2 * 16 + rh * 8 + g;
            float* op = out + ((size_t)b * Mm + m) * Cc + h * 64 + tig * 2;
            const float iv = inv[mt2][rh];
#pragma unroll
            for (int ntile = 0; ntile < 8; ntile++) {
                float2 v;
                v.x = o[mt2][ntile][rh * 2 + 0] * iv;
                v.y = o[mt2][ntile][rh * 2 + 1] * iv;
                *(float2*)(op + ntile * 8) = v;
            }
        }
    }
}

// ---------------------------------------------------------------------------
extern "C" void kernel_launch(void* const* d_in, const int* in_sizes, int n_in,
                              void* d_out, int out_size)
{
    const float* x     = (const float*)d_in[0];
    const int*   mask  = (const int*)  d_in[1];
    const float* Wq    = (const float*)d_in[2];
    const float* bq    = (const float*)d_in[3];
    const float* Wk    = (const float*)d_in[4];
    const float* bk    = (const float*)d_in[5];
    const float* Wv    = (const float*)d_in[6];
    const float* bv    = (const float*)d_in[7];
    const float* gamma = (const float*)d_in[8];
    float* out = (float*)d_out;

    static int attr_set = 0;
    if (!attr_set) {
        cudaFuncSetAttribute(proj_kernel,
                             cudaFuncAttributeMaxDynamicSharedMemorySize,
                             PNST * PSTG);
        attr_set = 1;
    }

    scan_kernel<<<Bb, 1024>>>(mask);
    conv_kernel<<<2240, 256>>>(Wq, Wk, Wv, x);

    dim3 pg((Bb * Mm) / 128, 12);
    proj_kernel<<<pg, 256, PNST * PSTG>>>(mask, bq, bk, bv);

    attn_kernel<<<BHt * (Mm / 128), 128>>>(gamma, out);
}